// round 9
// baseline (speedup 1.0000x reference)
#include <cuda_runtime.h>
#include <cstdint>

// LinearAttention n=4, L=8192, h=8, d=m=64 — mma.sync tf32.
// out[pair,l,m] = z_l * sum_d phiQ[l,d] * KV[d,m]
// KV[d,m] = sum_s phiK[s,d] V[s,m];  z_l = 1/(phiQ[l,:]·ksum + 1e-6)

#define NB 4
#define LL 8192
#define NH 8
#define DD 64
#define NPAIR 32
#define SPL 32
#define CHUNK (LL / SPL)       // 256
#define ROWS 32                // s rows per smem round
#define PADA 68                // qs row width: 64 data + 4 (gid-major conflict-free)
#define PADB 72                // Ks/Vs/kvs row width: 64 data + 8 (tig-major conflict-free)
#define NRND (CHUNK / ROWS)    // 8
#define TLQ 64                 // out l-tile rows
#define NT  4                  // l-tiles per out CTA

__device__ float g_kv_part[SPL * NPAIR * DD * DD];   // 16 MB
__device__ float g_ksum_part[SPL * NPAIR * DD];
__device__ float g_kv[NPAIR * DD * DD];              // tf32-rounded
__device__ float g_ksum[NPAIR * DD];                 // fp32

// ---------------- helpers ----------------
__device__ __forceinline__ uint32_t s2u(const void* p) {
    uint32_t a;
    asm("{ .reg .u64 t; cvta.to.shared.u64 t, %1; cvt.u32.u64 %0, t; }" : "=r"(a) : "l"(p));
    return a;
}
__device__ __forceinline__ uint32_t totf(float f) {
    uint32_t r; asm("cvt.rna.tf32.f32 %0, %1;" : "=r"(r) : "f"(f)); return r;
}
__device__ __forceinline__ float phi(float x) {
    x *= 0.35355339059327378f;            // 64^-0.25
    return x > 0.f ? x + 1.f : __expf(x);
}
__device__ __forceinline__ void mma8(float c[4], uint32_t a0, uint32_t a1,
                                     uint32_t a2, uint32_t a3,
                                     uint32_t b0, uint32_t b1) {
    asm volatile(
        "mma.sync.aligned.m16n8k8.row.col.f32.tf32.tf32.f32 "
        "{%0,%1,%2,%3}, {%4,%5,%6,%7}, {%8,%9}, {%0,%1,%2,%3};"
        : "+f"(c[0]), "+f"(c[1]), "+f"(c[2]), "+f"(c[3])
        : "r"(a0), "r"(a1), "r"(a2), "r"(a3), "r"(b0), "r"(b1));
}
__device__ __forceinline__ void cp16(uint32_t dst, const void* src) {
    asm volatile("cp.async.cg.shared.global [%0], [%1], 16;"
                 :: "r"(dst), "l"(src) : "memory");
}
#define CP_COMMIT() asm volatile("cp.async.commit_group;" ::: "memory")
#define CP_WAIT(N)  asm volatile("cp.async.wait_group %0;" :: "n"(N) : "memory")

// ---------------- kernel 1: KV partials (R4 body, 5-CTA bound) ----------------
__global__ __launch_bounds__(256, 5)
void kv_kernel(const float* __restrict__ K, const float* __restrict__ V) {
    __shared__ float Ks[ROWS][PADB];      // tf32-converted phi(K)
    __shared__ float Vs[2][ROWS][PADB];   // raw fp32 V (fed as tf32 bits)
    __shared__ float ksum_s[DD];

    const int tid = threadIdx.x, warp = tid >> 5, lane = tid & 31;
    const int gid = lane >> 2, tig = lane & 3;
    const int pair = blockIdx.y, b = pair >> 3, hh = pair & 7;
    const int split = blockIdx.x;
    const int wd = warp & 3, wm = warp >> 2;
    const int d0 = wd * 16, m0 = wm * 32;

    const size_t rstr = (size_t)NH * DD;
    const int lrow = tid >> 3, lcol = (tid & 7) * 8;
    const float* Kp = K + ((size_t)b * LL + split * CHUNK + lrow) * rstr + hh * DD + lcol;
    const float* Vp = V + ((size_t)b * LL + split * CHUNK + lrow) * rstr + hh * DD + lcol;
    const uint32_t vdst = s2u(&Vs[0][lrow][lcol]);
    const uint32_t bufB = ROWS * PADB * 4;

    if (tid < DD) ksum_s[tid] = 0.f;

    float acc[4][4];
    #pragma unroll
    for (int i = 0; i < 4; i++)
        #pragma unroll
        for (int j = 0; j < 4; j++) acc[i][j] = 0.f;
    float ks[8];
    #pragma unroll
    for (int j = 0; j < 8; j++) ks[j] = 0.f;

    cp16(vdst, Vp); cp16(vdst + 16, Vp + 4);
    CP_COMMIT();
    float4 ka = *(const float4*)Kp;
    float4 kb = *(const float4*)(Kp + 4);

    #pragma unroll
    for (int r = 0; r < NRND; r++) {
        if (r + 1 < NRND) {
            const size_t go = (size_t)(r + 1) * ROWS * rstr;
            const uint32_t so = ((r + 1) & 1) * bufB;
            cp16(vdst + so, Vp + go); cp16(vdst + so + 16, Vp + go + 4);
            CP_COMMIT();
        }
        {
            float p[8];
            p[0] = phi(ka.x); p[1] = phi(ka.y); p[2] = phi(ka.z); p[3] = phi(ka.w);
            p[4] = phi(kb.x); p[5] = phi(kb.y); p[6] = phi(kb.z); p[7] = phi(kb.w);
            #pragma unroll
            for (int j = 0; j < 8; j++) ks[j] += p[j];
            uint4 u0, u1;
            u0.x = totf(p[0]); u0.y = totf(p[1]); u0.z = totf(p[2]); u0.w = totf(p[3]);
            u1.x = totf(p[4]); u1.y = totf(p[5]); u1.z = totf(p[6]); u1.w = totf(p[7]);
            *(uint4*)&Ks[lrow][lcol]     = u0;
            *(uint4*)&Ks[lrow][lcol + 4] = u1;
        }
        if (r + 1 < NRND) {
            const size_t go = (size_t)(r + 1) * ROWS * rstr;
            ka = *(const float4*)(Kp + go);
            kb = *(const float4*)(Kp + go + 4);
            CP_WAIT(1);
        } else {
            CP_WAIT(0);
        }
        __syncthreads();

        const int buf = r & 1;
        #pragma unroll
        for (int kstp = 0; kstp < 4; kstp++) {
            const int sb = kstp * 8;
            const uint32_t a0 = __float_as_uint(Ks[sb + tig][d0 + gid]);
            const uint32_t a1 = __float_as_uint(Ks[sb + tig][d0 + gid + 8]);
            const uint32_t a2 = __float_as_uint(Ks[sb + tig + 4][d0 + gid]);
            const uint32_t a3 = __float_as_uint(Ks[sb + tig + 4][d0 + gid + 8]);
            #pragma unroll
            for (int nt = 0; nt < 4; nt++) {
                const int m = m0 + nt * 8 + gid;
                const uint32_t b0 = __float_as_uint(Vs[buf][sb + tig][m]);
                const uint32_t b1 = __float_as_uint(Vs[buf][sb + tig + 4][m]);
                mma8(acc[nt], a0, a1, a2, a3, b0, b1);
            }
        }
        __syncthreads();
    }

    float* dst = g_kv_part + ((size_t)split * NPAIR + pair) * DD * DD;
    const int dlo = d0 + gid;
    #pragma unroll
    for (int nt = 0; nt < 4; nt++) {
        const int m = m0 + nt * 8 + 2 * tig;
        *(float2*)(dst + dlo * DD + m)       = make_float2(acc[nt][0], acc[nt][1]);
        *(float2*)(dst + (dlo + 8) * DD + m) = make_float2(acc[nt][2], acc[nt][3]);
    }
    #pragma unroll
    for (int j = 0; j < 8; j++) {
        ks[j] += __shfl_xor_sync(0xffffffffu, ks[j], 8);
        ks[j] += __shfl_xor_sync(0xffffffffu, ks[j], 16);
    }
    if (lane < 8) {
        #pragma unroll
        for (int j = 0; j < 8; j++)
            atomicAdd(&ksum_s[lane * 8 + j], ks[j]);
    }
    __syncthreads();
    if (tid < DD)
        g_ksum_part[((size_t)split * NPAIR + pair) * DD + tid] = ksum_s[tid];
}

// ---------------- reduce partials ----------------
__global__ void reduce_kernel() {
    const int i = blockIdx.x * blockDim.x + threadIdx.x;
    if (i < NPAIR * DD * DD) {
        float s = 0.f;
        #pragma unroll
        for (int p = 0; p < SPL; p++) s += g_kv_part[(size_t)p * NPAIR * DD * DD + i];
        g_kv[i] = __uint_as_float(totf(s));
    } else {
        const int j = i - NPAIR * DD * DD;
        if (j < NPAIR * DD) {
            float s = 0.f;
            #pragma unroll
            for (int p = 0; p < SPL; p++) s += g_ksum_part[p * NPAIR * DD + j];
            g_ksum[j] = s;
        }
    }
}

// ---------------- kernel 2: output GEMM (persistent 4-tile, single buffer) ----
// dynamic smem: qs[64][PADA] + kvs[64][PADB] + zs[64]  = 36096 B -> 6 CTAs/SM
#define K2_SMEM ((TLQ * PADA + DD * PADB + TLQ) * 4)

__global__ __launch_bounds__(256, 6)
void out_kernel(const float* __restrict__ Q, float* __restrict__ O) {
    extern __shared__ float sm2[];
    float (*qs)[PADA]  = (float(*)[PADA])sm2;
    float (*kvs)[PADB] = (float(*)[PADB])(sm2 + TLQ * PADA);
    float* zs = sm2 + TLQ * PADA + DD * PADB;

    const int tid = threadIdx.x, warp = tid >> 5, lane = tid & 31;
    const int gid = lane >> 2, tig = lane & 3;
    const int pair = blockIdx.y, b = pair >> 3, hh = pair & 7;
    const int lbase = blockIdx.x * (TLQ * NT);

    // KV tile via cp.async, once per CTA
    {
        const float* kvp = g_kv + (size_t)pair * DD * DD;
        #pragma unroll
        for (int k = 0; k < 4; k++) {
            const int f = (k * 256 + tid) * 4;
            cp16(s2u(&kvs[f >> 6][f & 63]), kvp + f);
        }
        CP_COMMIT();
    }

    // per-thread q-prep mapping: 4 threads per row, 16 d each
    const int row = tid >> 2, qtr = tid & 3;
    const float* ksg = g_ksum + pair * DD + qtr * 16;
    float4 k4[4];
    #pragma unroll
    for (int i = 0; i < 4; i++) k4[i] = __ldg((const float4*)(ksg + i * 4));

    const float* qbase = Q + ((size_t)b * LL + lbase + row) * (NH * DD)
                           + (size_t)hh * DD + qtr * 16;
    float4 qv[4];
    #pragma unroll
    for (int i = 0; i < 4; i++) qv[i] = *(const float4*)(qbase + i * 4);

    const int lw = (warp & 3) * 16;
    const int m0 = (warp >> 2) * 32;

    #pragma unroll
    for (int t = 0; t < NT; t++) {
        // phi + z-dot + tf32 STS (from prefetched registers)
        {
            float accz = 0.f;
            #pragma unroll
            for (int i = 0; i < 4; i++) {
                float4 q4 = qv[i];
                q4.x = phi(q4.x); q4.y = phi(q4.y); q4.z = phi(q4.z); q4.w = phi(q4.w);
                accz += q4.x * k4[i].x + q4.y * k4[i].y
                      + q4.z * k4[i].z + q4.w * k4[i].w;
                uint4 u;
                u.x = totf(q4.x); u.y = totf(q4.y); u.z = totf(q4.z); u.w = totf(q4.w);
                *(uint4*)&qs[row][qtr * 16 + i * 4] = u;
            }
            accz += __shfl_xor_sync(0xffffffffu, accz, 1);
            accz += __shfl_xor_sync(0xffffffffu, accz, 2);
            if (qtr == 0) zs[row] = 1.f / (accz + 1e-6f);
        }
        if (t == 0) CP_WAIT(0);
        __syncthreads();                        // staging visible

        // prefetch Q(t+1) — overlaps MMA + store below
        if (t + 1 < NT) {
            const float* qn = qbase + (size_t)TLQ * (t + 1) * (NH * DD);
            #pragma unroll
            for (int i = 0; i < 4; i++) qv[i] = *(const float4*)(qn + i * 4);
        }

        // 16l x 32m per warp
        float acc[4][4];
        #pragma unroll
        for (int i = 0; i < 4; i++)
            #pragma unroll
            for (int j = 0; j < 4; j++) acc[i][j] = 0.f;

        #pragma unroll
        for (int kk = 0; kk < 8; kk++) {
            const int k0 = kk * 8;
            const uint32_t a0 = __float_as_uint(qs[lw + gid][k0 + tig]);
            const uint32_t a1 = __float_as_uint(qs[lw + gid + 8][k0 + tig]);
            const uint32_t a2 = __float_as_uint(qs[lw + gid][k0 + tig + 4]);
            const uint32_t a3 = __float_as_uint(qs[lw + gid + 8][k0 + tig + 4]);
            #pragma unroll
            for (int nt = 0; nt < 4; nt++) {
                const int m = m0 + nt * 8 + gid;
                const uint32_t b0 = __float_as_uint(kvs[k0 + tig][m]);
                const uint32_t b1 = __float_as_uint(kvs[k0 + tig + 4][m]);
                mma8(acc[nt], a0, a1, a2, a3, b0, b1);
            }
        }

        const float z0 = zs[lw + gid];
        const float z1 = zs[lw + gid + 8];
        float* dst = O + ((size_t)pair * LL + lbase + t * TLQ + lw + gid) * DD;
        #pragma unroll
        for (int nt = 0; nt < 4; nt++) {
            const int m = m0 + nt * 8 + 2 * tig;
            *(float2*)(dst + m)          = make_float2(acc[nt][0] * z0, acc[nt][1] * z0);
            *(float2*)(dst + 8 * DD + m) = make_float2(acc[nt][2] * z1, acc[nt][3] * z1);
        }
        if (t + 1 < NT) __syncthreads();        // MMA reads done before next staging write
    }
}

// ---------------- launch ----------------
extern "C" void kernel_launch(void* const* d_in, const int* in_sizes, int n_in,
                              void* d_out, int out_size) {
    const float* Q = (const float*)d_in[0];
    const float* K = (const float*)d_in[1];
    const float* V = (const float*)d_in[2];
    float* O = (float*)d_out;

    cudaFuncSetAttribute(out_kernel, cudaFuncAttributeMaxDynamicSharedMemorySize, K2_SMEM);

    kv_kernel<<<dim3(SPL, NPAIR), 256>>>(K, V);
    reduce_kernel<<<(NPAIR * DD * DD + NPAIR * DD + 255) / 256, 256>>>();
    out_kernel<<<dim3(LL / (TLQ * NT), NPAIR), 256, K2_SMEM>>>(Q, O);
}

// round 11
// speedup vs baseline: 1.2979x; 1.2979x over previous
#include <cuda_runtime.h>
#include <cuda_fp16.h>
#include <cstdint>

// LinearAttention n=4, L=8192, h=8, d=m=64.
// kv: mma.sync tf32 (proven R8). out: mma.sync f16 m16n8k16 + ldmatrix.
// out[pair,l,m] = z_l * sum_d phiQ[l,d] * KV[d,m]
// KV[d,m] = sum_s phiK[s,d] V[s,m];  z_l = 1/(phiQ[l,:]·ksum + 1e-6)

#define NB 4
#define LL 8192
#define NH 8
#define DD 64
#define NPAIR 32
#define SPL 32
#define CHUNK (LL / SPL)       // 256
#define ROWS 32
#define PADB 72                // kv fp32 arrays (proven)
#define NRND (CHUNK / ROWS)    // 8
#define TLQ 64                 // out l-tile rows
#define NT  4                  // l-tiles per out CTA
#define PH  72                 // out f16 row pitch in halves (144 B)

__device__ float  g_kv_part[SPL * NPAIR * DD * DD];
__device__ float  g_ksum_part[SPL * NPAIR * DD];
__device__ __half g_kvh[NPAIR * DD * DD];            // f16 KV for out
__device__ float  g_ksum[NPAIR * DD];                // fp32

// ---------------- helpers ----------------
__device__ __forceinline__ uint32_t s2u(const void* p) {
    uint32_t a;
    asm("{ .reg .u64 t; cvta.to.shared.u64 t, %1; cvt.u32.u64 %0, t; }" : "=r"(a) : "l"(p));
    return a;
}
__device__ __forceinline__ uint32_t totf(float f) {
    uint32_t r; asm("cvt.rna.tf32.f32 %0, %1;" : "=r"(r) : "f"(f)); return r;
}
__device__ __forceinline__ float phi(float x) {
    x *= 0.35355339059327378f;            // 64^-0.25
    return x > 0.f ? x + 1.f : __expf(x);
}
__device__ __forceinline__ uint32_t packh2(float lo, float hi) {
    __half2 h = __floats2half2_rn(lo, hi);
    return *reinterpret_cast<uint32_t*>(&h);
}
__device__ __forceinline__ void mma8(float c[4], uint32_t a0, uint32_t a1,
                                     uint32_t a2, uint32_t a3,
                                     uint32_t b0, uint32_t b1) {
    asm volatile(
        "mma.sync.aligned.m16n8k8.row.col.f32.tf32.tf32.f32 "
        "{%0,%1,%2,%3}, {%4,%5,%6,%7}, {%8,%9}, {%0,%1,%2,%3};"
        : "+f"(c[0]), "+f"(c[1]), "+f"(c[2]), "+f"(c[3])
        : "r"(a0), "r"(a1), "r"(a2), "r"(a3), "r"(b0), "r"(b1));
}
__device__ __forceinline__ void mma16(float c[4], uint32_t a0, uint32_t a1,
                                      uint32_t a2, uint32_t a3,
                                      uint32_t b0, uint32_t b1) {
    asm volatile(
        "mma.sync.aligned.m16n8k16.row.col.f32.f16.f16.f32 "
        "{%0,%1,%2,%3}, {%4,%5,%6,%7}, {%8,%9}, {%0,%1,%2,%3};"
        : "+f"(c[0]), "+f"(c[1]), "+f"(c[2]), "+f"(c[3])
        : "r"(a0), "r"(a1), "r"(a2), "r"(a3), "r"(b0), "r"(b1));
}
#define LDSM_X4(r0, r1, r2, r3, addr) \
    asm volatile("ldmatrix.sync.aligned.m8n8.x4.shared.b16 {%0,%1,%2,%3}, [%4];" \
                 : "=r"(r0), "=r"(r1), "=r"(r2), "=r"(r3) : "r"(addr))
#define LDSM_X4T(r0, r1, r2, r3, addr) \
    asm volatile("ldmatrix.sync.aligned.m8n8.x4.trans.shared.b16 {%0,%1,%2,%3}, [%4];" \
                 : "=r"(r0), "=r"(r1), "=r"(r2), "=r"(r3) : "r"(addr))
__device__ __forceinline__ void cp16(uint32_t dst, const void* src) {
    asm volatile("cp.async.cg.shared.global [%0], [%1], 16;"
                 :: "r"(dst), "l"(src) : "memory");
}
#define CP_COMMIT() asm volatile("cp.async.commit_group;" ::: "memory")
#define CP_WAIT(N)  asm volatile("cp.async.wait_group %0;" :: "n"(N) : "memory")

// ---------------- kernel 1: KV partials (R8-proven, tf32) ----------------
__global__ __launch_bounds__(256)
void kv_kernel(const float* __restrict__ K, const float* __restrict__ V) {
    __shared__ float Ks[ROWS][PADB];
    __shared__ float Vs[2][ROWS][PADB];
    __shared__ float ksum_s[DD];

    const int tid = threadIdx.x, warp = tid >> 5, lane = tid & 31;
    const int gid = lane >> 2, tig = lane & 3;
    const int pair = blockIdx.y, b = pair >> 3, hh = pair & 7;
    const int split = blockIdx.x;
    const int wd = warp & 3, wm = warp >> 2;
    const int d0 = wd * 16, m0 = wm * 32;

    const size_t rstr = (size_t)NH * DD;
    const int lrow = tid >> 3, lcol = (tid & 7) * 8;
    const float* Kp = K + ((size_t)b * LL + split * CHUNK + lrow) * rstr + hh * DD + lcol;
    const float* Vp = V + ((size_t)b * LL + split * CHUNK + lrow) * rstr + hh * DD + lcol;
    const uint32_t vdst = s2u(&Vs[0][lrow][lcol]);
    const uint32_t bufB = ROWS * PADB * 4;

    if (tid < DD) ksum_s[tid] = 0.f;

    float acc[4][4];
    #pragma unroll
    for (int i = 0; i < 4; i++)
        #pragma unroll
        for (int j = 0; j < 4; j++) acc[i][j] = 0.f;
    float ks[8];
    #pragma unroll
    for (int j = 0; j < 8; j++) ks[j] = 0.f;

    cp16(vdst, Vp); cp16(vdst + 16, Vp + 4);
    CP_COMMIT();
    float4 ka = *(const float4*)Kp;
    float4 kb = *(const float4*)(Kp + 4);

    #pragma unroll
    for (int r = 0; r < NRND; r++) {
        if (r + 1 < NRND) {
            const size_t go = (size_t)(r + 1) * ROWS * rstr;
            const uint32_t so = ((r + 1) & 1) * bufB;
            cp16(vdst + so, Vp + go); cp16(vdst + so + 16, Vp + go + 4);
            CP_COMMIT();
        }
        {
            float p[8];
            p[0] = phi(ka.x); p[1] = phi(ka.y); p[2] = phi(ka.z); p[3] = phi(ka.w);
            p[4] = phi(kb.x); p[5] = phi(kb.y); p[6] = phi(kb.z); p[7] = phi(kb.w);
            #pragma unroll
            for (int j = 0; j < 8; j++) ks[j] += p[j];
            uint4 u0, u1;
            u0.x = totf(p[0]); u0.y = totf(p[1]); u0.z = totf(p[2]); u0.w = totf(p[3]);
            u1.x = totf(p[4]); u1.y = totf(p[5]); u1.z = totf(p[6]); u1.w = totf(p[7]);
            *(uint4*)&Ks[lrow][lcol]     = u0;
            *(uint4*)&Ks[lrow][lcol + 4] = u1;
        }
        if (r + 1 < NRND) {
            const size_t go = (size_t)(r + 1) * ROWS * rstr;
            ka = *(const float4*)(Kp + go);
            kb = *(const float4*)(Kp + go + 4);
            CP_WAIT(1);
        } else {
            CP_WAIT(0);
        }
        __syncthreads();

        const int buf = r & 1;
        #pragma unroll
        for (int kstp = 0; kstp < 4; kstp++) {
            const int sb = kstp * 8;
            const uint32_t a0 = __float_as_uint(Ks[sb + tig][d0 + gid]);
            const uint32_t a1 = __float_as_uint(Ks[sb + tig][d0 + gid + 8]);
            const uint32_t a2 = __float_as_uint(Ks[sb + tig + 4][d0 + gid]);
            const uint32_t a3 = __float_as_uint(Ks[sb + tig + 4][d0 + gid + 8]);
            #pragma unroll
            for (int nt = 0; nt < 4; nt++) {
                const int m = m0 + nt * 8 + gid;
                const uint32_t b0 = __float_as_uint(Vs[buf][sb + tig][m]);
                const uint32_t b1 = __float_as_uint(Vs[buf][sb + tig + 4][m]);
                mma8(acc[nt], a0, a1, a2, a3, b0, b1);
            }
        }
        __syncthreads();
    }

    float* dst = g_kv_part + ((size_t)split * NPAIR + pair) * DD * DD;
    const int dlo = d0 + gid;
    #pragma unroll
    for (int nt = 0; nt < 4; nt++) {
        const int m = m0 + nt * 8 + 2 * tig;
        *(float2*)(dst + dlo * DD + m)       = make_float2(acc[nt][0], acc[nt][1]);
        *(float2*)(dst + (dlo + 8) * DD + m) = make_float2(acc[nt][2], acc[nt][3]);
    }
    #pragma unroll
    for (int j = 0; j < 8; j++) {
        ks[j] += __shfl_xor_sync(0xffffffffu, ks[j], 8);
        ks[j] += __shfl_xor_sync(0xffffffffu, ks[j], 16);
    }
    if (lane < 8) {
        #pragma unroll
        for (int j = 0; j < 8; j++)
            atomicAdd(&ksum_s[lane * 8 + j], ks[j]);
    }
    __syncthreads();
    if (tid < DD)
        g_ksum_part[((size_t)split * NPAIR + pair) * DD + tid] = ksum_s[tid];
}

// ---------------- reduce partials (KV -> f16, ksum -> fp32) ----------------
__global__ void reduce_kernel() {
    const int i = blockIdx.x * blockDim.x + threadIdx.x;
    if (i < NPAIR * DD * DD) {
        float s = 0.f;
        #pragma unroll
        for (int p = 0; p < SPL; p++) s += g_kv_part[(size_t)p * NPAIR * DD * DD + i];
        g_kvh[i] = __float2half_rn(s);
    } else {
        const int j = i - NPAIR * DD * DD;
        if (j < NPAIR * DD) {
            float s = 0.f;
            #pragma unroll
            for (int p = 0; p < SPL; p++) s += g_ksum_part[p * NPAIR * DD + j];
            g_ksum[j] = s;
        }
    }
}

// ---------------- kernel 2: output GEMM (f16 m16n8k16 + ldmatrix) ----------
// smem: qs f16 [2][64][PH] (18432 B) | kvs f16 [64][PH] (9216 B) | zs [2][64] f32
#define QS_BYTES  (2 * TLQ * PH * 2)
#define KVS_BYTES (DD * PH * 2)
#define K2_SMEM   (QS_BYTES + KVS_BYTES + 2 * TLQ * 4)

__global__ __launch_bounds__(256)
void out_kernel(const float* __restrict__ Q, float* __restrict__ O) {
    extern __shared__ char smx[];
    const uint32_t smb = s2u(smx);
    float* zsb = (float*)(smx + QS_BYTES + KVS_BYTES);

    const int tid = threadIdx.x, warp = tid >> 5, lane = tid & 31;
    const int gid = lane >> 2, tig = lane & 3;
    const int pair = blockIdx.y, b = pair >> 3, hh = pair & 7;
    const int lbase = blockIdx.x * (TLQ * NT);

    // KV tile (f16) via cp.async, once per CTA
    {
        const int krow = tid >> 2, kck = tid & 3;
        const __half* src = g_kvh + (size_t)pair * DD * DD + krow * DD + kck * 16;
        const uint32_t dst = smb + QS_BYTES + (uint32_t)krow * (PH * 2) + kck * 32;
        cp16(dst, src); cp16(dst + 16, src + 8);   // +16 B on both sides (FIXED)
    }
    CP_COMMIT();

    // q-prep mapping: 4 threads per row, 16 d each
    const int row = tid >> 2, qtr = tid & 3;
    const float* ksg = g_ksum + pair * DD + qtr * 16;
    float4 k4[4];
    #pragma unroll
    for (int i = 0; i < 4; i++) k4[i] = __ldg((const float4*)(ksg + i * 4));

    const float* qbase = Q + ((size_t)b * LL + lbase + row) * (NH * DD)
                           + (size_t)hh * DD + qtr * 16;
    float4 qv[4];
    #pragma unroll
    for (int i = 0; i < 4; i++) qv[i] = *(const float4*)(qbase + i * 4);

    const int lw = (warp & 3) * 16;
    const int m0w = (warp >> 2) * 32;

    // ldmatrix lane decomposition
    const int lr8  = lane & 7;
    const int seld = (lane >> 3) & 1;   // +8 row-group
    const int selc = (lane >> 4) & 1;   // +8 col-group
    // A (qs, non-trans): stored row l = lw + lr8 + seld*8; col halves kk*16 + selc*8
    const uint32_t a_row_bytes = (uint32_t)(lw + lr8 + seld * 8) * (PH * 2);
    // B (kvs, trans): stored row d = kk*16 + lr8 + seld*8; col m = m0w + ntp*16 + selc*8
    const uint32_t b_base = smb + QS_BYTES
                          + (uint32_t)(lr8 + seld * 8) * (PH * 2)
                          + (uint32_t)(m0w + selc * 8) * 2;

    #pragma unroll
    for (int t = 0; t < NT; t++) {
        const int buf = t & 1;
        const uint32_t qs_off = (uint32_t)buf * (TLQ * PH * 2);
        float* zs = zsb + buf * TLQ;

        // stage: phi + fp32 z-dot + f16 pack -> qs[buf]
        {
            float accz = 0.f;
            uint32_t h[8];
            #pragma unroll
            for (int i = 0; i < 4; i++) {
                float4 q4 = qv[i];
                q4.x = phi(q4.x); q4.y = phi(q4.y); q4.z = phi(q4.z); q4.w = phi(q4.w);
                accz += q4.x * k4[i].x + q4.y * k4[i].y
                      + q4.z * k4[i].z + q4.w * k4[i].w;
                h[i * 2]     = packh2(q4.x, q4.y);
                h[i * 2 + 1] = packh2(q4.z, q4.w);
            }
            accz += __shfl_xor_sync(0xffffffffu, accz, 1);
            accz += __shfl_xor_sync(0xffffffffu, accz, 2);
            char* qdst = smx + qs_off + (uint32_t)row * (PH * 2) + qtr * 32;
            *(uint4*)qdst        = make_uint4(h[0], h[1], h[2], h[3]);
            *(uint4*)(qdst + 16) = make_uint4(h[4], h[5], h[6], h[7]);
            if (qtr == 0) zs[row] = 1.f / (accz + 1e-6f);
        }
        if (t == 0) CP_WAIT(0);
        __syncthreads();

        // prefetch Q(t+1)
        if (t + 1 < NT) {
            const float* qn = qbase + (size_t)TLQ * (t + 1) * (NH * DD);
            #pragma unroll
            for (int i = 0; i < 4; i++) qv[i] = *(const float4*)(qn + i * 4);
        }

        float acc[4][4];
        #pragma unroll
        for (int i = 0; i < 4; i++)
            #pragma unroll
            for (int j = 0; j < 4; j++) acc[i][j] = 0.f;

        const uint32_t abase = smb + qs_off + a_row_bytes;
        #pragma unroll
        for (int kk = 0; kk < 4; kk++) {
            uint32_t a0, a1, a2, a3;
            LDSM_X4(a0, a1, a2, a3, abase + (uint32_t)(kk * 16 + selc * 8) * 2);
            #pragma unroll
            for (int ntp = 0; ntp < 2; ntp++) {
                uint32_t b0, b1, b2, b3;
                LDSM_X4T(b0, b1, b2, b3,
                         b_base + (uint32_t)(kk * 16) * (PH * 2) + (uint32_t)(ntp * 16) * 2);
                mma16(acc[ntp * 2],     a0, a1, a2, a3, b0, b1);
                mma16(acc[ntp * 2 + 1], a0, a1, a2, a3, b2, b3);
            }
        }

        const float z0 = zs[lw + gid];
        const float z1 = zs[lw + gid + 8];
        float* dst = O + ((size_t)pair * LL + lbase + t * TLQ + lw + gid) * DD;
        #pragma unroll
        for (int nt = 0; nt < 4; nt++) {
            const int m = m0w + nt * 8 + 2 * tig;
            *(float2*)(dst + m)          = make_float2(acc[nt][0] * z0, acc[nt][1] * z0);
            *(float2*)(dst + 8 * DD + m) = make_float2(acc[nt][2] * z1, acc[nt][3] * z1);
        }
        // no trailing sync needed: next tile writes the other qs buffer
    }
}

// ---------------- launch ----------------
extern "C" void kernel_launch(void* const* d_in, const int* in_sizes, int n_in,
                              void* d_out, int out_size) {
    const float* Q = (const float*)d_in[0];
    const float* K = (const float*)d_in[1];
    const float* V = (const float*)d_in[2];
    float* O = (float*)d_out;

    cudaFuncSetAttribute(out_kernel, cudaFuncAttributeMaxDynamicSharedMemorySize, K2_SMEM);

    kv_kernel<<<dim3(SPL, NPAIR), 256>>>(K, V);
    reduce_kernel<<<(NPAIR * DD * DD + NPAIR * DD + 255) / 256, 256>>>();
    out_kernel<<<dim3(LL / (TLQ * NT), NPAIR), 256, K2_SMEM>>>(Q, O);
}